// round 17
// baseline (speedup 1.0000x reference)
#include <cuda_runtime.h>
#include <cstdint>

// Problem constants
#define TD     64
#define MODES  16
#define MRI    32          // 2*MODES
#define PD     16384       // N*D pixels
#define SCOL   1048576     // PD*64 floats per time row
#define TILE_P 8
#define NBLK   (PD / TILE_P)   // 2048 CTAs
#define NTHR   256

typedef unsigned long long u64;

// tf32-rounded, k-permuted, n-swizzled weights:
// g_W3f[m][comp][n][ S(k) ^ ((n&3)<<3) ], comp 0=WR, 1=WI.  512 KB, L2-resident.
__device__ __align__(16) float g_W3f[MODES * 2 * 64 * 64];

// ---------- compile-time DFT coefficients ----------
__host__ __device__ constexpr float cos64(int k) {
    constexpr float COSQ[17] = {
        1.0f,
        0.995184726672197f, 0.980785280403230f, 0.956940335732209f,
        0.923879532511287f, 0.881921264348355f, 0.831469612302545f,
        0.773010453362737f, 0.707106781186548f, 0.634393284163645f,
        0.555570233019602f, 0.471396736825998f, 0.382683432365090f,
        0.290284677254462f, 0.195090322016128f, 0.098017140329561f,
        0.0f
    };
    k &= 63;
    float s = 1.0f;
    if (k > 32) k = 64 - k;
    if (k > 16) { k = 32 - k; s = -1.0f; }
    return s * COSQ[k];
}
__host__ __device__ constexpr float alpha64(int m) {
    return ((m == 0) ? 1.0f : 2.0f) / 64.0f;
}

// mma-fragment channel permutation within each 8-wide k-tile:
// logical r<4 -> 2r ; r>=4 -> 2(r-4)+1
__host__ __device__ __forceinline__ int SPERM(int c) {
    int r = c & 7;
    int s = (r < 4) ? (2 * r) : (2 * (r - 4) + 1);
    return (c & ~7) | s;
}

// ---------- helpers ----------
__device__ __forceinline__ u64 pack2(float a, float b) {
    u64 r;
    asm("mov.b64 %0, {%1, %2};" : "=l"(r) : "f"(a), "f"(b));
    return r;
}
__device__ __forceinline__ void unpack2(u64 v, float &lo, float &hi) {
    asm("mov.b64 {%0, %1}, %2;" : "=f"(lo), "=f"(hi) : "l"(v));
}
__device__ __forceinline__ uint32_t f2tf32(float x) {
    uint32_t r;
    asm("cvt.rna.tf32.f32 %0, %1;" : "=r"(r) : "f"(x));
    return r;
}
__device__ __forceinline__ void mma_tf32(float d[4],
                                         uint32_t a0, uint32_t a1, uint32_t a2, uint32_t a3,
                                         uint32_t b0, uint32_t b1) {
    asm("mma.sync.aligned.m16n8k8.row.col.f32.tf32.tf32.f32 "
        "{%0,%1,%2,%3},{%4,%5,%6,%7},{%8,%9},{%0,%1,%2,%3};"
        : "+f"(d[0]), "+f"(d[1]), "+f"(d[2]), "+f"(d[3])
        : "r"(a0), "r"(a1), "r"(a2), "r"(a3), "r"(b0), "r"(b1));
}

// =====================================================================
// One-time weight repack into the fragment-ready image.
// =====================================================================
__global__ void __launch_bounds__(256) w_pack(const float* __restrict__ w) {
    int idx = blockIdx.x * 256 + threadIdx.x;         // 0 .. 131071
    int m    = idx >> 13;
    int comp = (idx >> 12) & 1;
    int n    = (idx >> 6) & 63;
    int k    = idx & 63;
    float v = w[(((long)k * 64 + n) * MODES + m) * 2 + comp];
    int dst = m * 8192 + (comp * 64 + n) * 64 + (SPERM(k) ^ ((n & 3) << 3));
    reinterpret_cast<uint32_t*>(g_W3f)[dst] = f2tf32(v);
}

// =====================================================================
// Fused spectral conv. 256 threads, 8 pixels/CTA, 64 KB smem,
// 2 CTAs per SM (independent stage overlap).
// smem: XY [32 mri][8 px][64 f32]
//   X rows: tf32 bits, k-permuted cols, XOR-swizzled by (px&3)<<3 (f32 units)
//   Y rows: f32, logical cols, XOR-swizzled by (px&3)<<3
// Stage 2: warp owns 2 modes — zero barriers. One mma covers M=16 as
// [XR(8px); XI(8px)] stacked: D1=[XR;XI]*WR, D2=[XR;XI]*WI;
// YR = D1.top - D2.bot, YI = D2.top + D1.bot (all thread-local in the
// m16n8k8 fragment map: rows g and g+8 live in the same thread).
// Only 2 __syncthreads total.
// =====================================================================
__global__ void __launch_bounds__(NTHR, 2) fused_spectral(const float* __restrict__ x,
                                                          float* __restrict__ out) {
    extern __shared__ __align__(16) char smem[];
    u64*      XY64 = reinterpret_cast<u64*>(smem);
    uint32_t* XYu  = reinterpret_cast<uint32_t*>(smem);

    const int tid = threadIdx.x;
    const int p0  = blockIdx.x * TILE_P;

    // =============== Stage 1: truncated rfft (folded, FFMA-imm) ===============
    // 256 thr = 8 px x 32 channel-pairs, single pass.
    {
        const int cp = tid & 31;
        const int p  = tid >> 5;             // 0..7, warp-uniform
        const int s0 = SPERM(2 * cp);
        const int s1 = SPERM(2 * cp + 1);
        const int swz = (p & 3) << 3;
        const u64* xp = reinterpret_cast<const u64*>(x) + (long)(p0 + p) * 32 + cp;

        float XcL[16], XcH[16], XsL[16], XsH[16];
        {
            float x0L, x0H, x32L, x32H;
            unpack2(xp[0], x0L, x0H);
            unpack2(xp[32 * (SCOL / 2)], x32L, x32H);
#pragma unroll
            for (int m = 0; m < 16; m++) {
                if (m & 1) { XcL[m] = x0L - x32L; XcH[m] = x0H - x32H; }
                else       { XcL[m] = x0L + x32L; XcH[m] = x0H + x32H; }
                XsL[m] = 0.0f; XsH[m] = 0.0f;
            }
        }

#pragma unroll
        for (int t = 1; t < 32; t++) {
            float aL, aH, bL, bH;
            unpack2(xp[(long)t * (SCOL / 2)], aL, aH);
            unpack2(xp[(long)(64 - t) * (SCOL / 2)], bL, bH);
            const float eL = aL + bL, eH = aH + bH;
            const float oL = aL - bL, oH = aH - bH;
            XcL[0] += eL; XcH[0] += eH;
#pragma unroll
            for (int m = 1; m < 16; m++) {
                const float fc = cos64(m * t);
                const float fs = cos64(m * t + 16);
                if (fc != 0.0f) {
                    XcL[m] = fmaf(eL, fc, XcL[m]);
                    XcH[m] = fmaf(eH, fc, XcH[m]);
                }
                if (fs != 0.0f) {
                    XsL[m] = fmaf(oL, fs, XsL[m]);
                    XsH[m] = fmaf(oH, fs, XsH[m]);
                }
            }
        }

#pragma unroll
        for (int m = 0; m < 16; m++) {
            const int rowR = ((2 * m)     * TILE_P + p) * 64;
            const int rowI = ((2 * m + 1) * TILE_P + p) * 64;
            XYu[rowR + (s0 ^ swz)] = f2tf32(XcL[m]);
            XYu[rowR + (s1 ^ swz)] = f2tf32(XcH[m]);
            XYu[rowI + (s0 ^ swz)] = f2tf32(XsL[m]);
            XYu[rowI + (s1 ^ swz)] = f2tf32(XsH[m]);
        }
    }

    __syncthreads();   // X published (sync #1)

    // =============== Stage 2: complex channel mix (tensor, barrier-free) ===============
    // Warp w owns modes 2w, 2w+1. A = [XR(8px); XI(8px)] stacked in M.
    {
        const int lane = tid & 31;
        const int wrp  = tid >> 5;          // 0..7
        const int g    = lane >> 2;         // 0..7  (= pixel)
        const int t    = lane & 3;          // 0..3
        const int swzg = (g & 3) << 2;      // u64-index XOR
        const u64* gW64 = reinterpret_cast<const u64*>(g_W3f);

#pragma unroll 1
        for (int mm = 0; mm < 2; mm++) {
            const int m = 2 * wrp + mm;
            const u64* Wm = gW64 + (long)m * 4096;
            const int rowR = (2 * m)     * TILE_P * 32;   // u64 base of XR rows
            const int rowI = (2 * m + 1) * TILE_P * 32;

            float d1[8][4], d2[8][4];
#pragma unroll
            for (int nt = 0; nt < 8; nt++)
#pragma unroll
                for (int j = 0; j < 4; j++) { d1[nt][j] = 0.f; d2[nt][j] = 0.f; }

#pragma unroll
            for (int kt = 0; kt < 8; kt++) {
                const int col = (kt * 4 + t) ^ swzg;
                u64 ar = XY64[rowR + g * 32 + col];   // XR px g  (mma row g)
                u64 ai = XY64[rowI + g * 32 + col];   // XI px g  (mma row g+8)
                uint2 AR = *reinterpret_cast<uint2*>(&ar);
                uint2 AI = *reinterpret_cast<uint2*>(&ai);

#pragma unroll
                for (int nt = 0; nt < 8; nt++) {
                    u64 br = __ldg(&Wm[(nt * 8 + g) * 32 + col]);        // WR (L2)
                    u64 bi = __ldg(&Wm[(64 + nt * 8 + g) * 32 + col]);   // WI (L2)
                    uint2 BR = *reinterpret_cast<uint2*>(&br);
                    uint2 BI = *reinterpret_cast<uint2*>(&bi);

                    mma_tf32(d1[nt], AR.x, AI.x, AR.y, AI.y, BR.x, BR.y);
                    mma_tf32(d2[nt], AR.x, AI.x, AR.y, AI.y, BI.x, BI.y);
                }
            }

            // Epilogue: YR = D1.top - D2.bot, YI = D2.top + D1.bot.
            // All X reads for this mode done; rows private to this warp.
#pragma unroll
            for (int nt = 0; nt < 8; nt++) {
                const int ecol = (nt * 4 + t) ^ swzg;
                XY64[rowR + g * 32 + ecol] =
                    pack2(d1[nt][0] - d2[nt][2], d1[nt][1] - d2[nt][3]);   // YR px g
                XY64[rowI + g * 32 + ecol] =
                    pack2(d2[nt][0] + d1[nt][2], d2[nt][1] + d1[nt][3]);   // YI px g
            }
        }
    }

    __syncthreads();   // Y complete (sync #2)

    // =============== Stage 3: truncated irfft (folded, FFMA-imm) ===============
    // 256 thr = 8 px x 32 output-pairs, single pass.
    {
        const int op  = tid & 31;
        const int p   = tid >> 5;
        const int col = op ^ ((p & 3) << 2);   // u64 col (swizzled)

        float yRL[16], yRH[16], yIL[16], yIH[16];
#pragma unroll
        for (int m = 0; m < 16; m++) {
            unpack2(XY64[((2 * m)     * TILE_P + p) * 32 + col], yRL[m], yRH[m]);
            unpack2(XY64[((2 * m + 1) * TILE_P + p) * 32 + col], yIL[m], yIH[m]);
        }

        u64* outp = reinterpret_cast<u64*>(out) + (long)(p0 + p) * 32 + op;

        // t = 0
        {
            float c0 = 0.0f, c1 = 0.0f;
#pragma unroll
            for (int m = 0; m < 16; m++) {
                const float gc = alpha64(m);
                c0 = fmaf(yRL[m], gc, c0);
                c1 = fmaf(yRH[m], gc, c1);
            }
            outp[0] = pack2(c0, c1);
        }
        // t = 32
        {
            float c0 = 0.0f, c1 = 0.0f;
#pragma unroll
            for (int m = 0; m < 16; m++) {
                const float gc = (m & 1) ? -alpha64(m) : alpha64(m);
                c0 = fmaf(yRL[m], gc, c0);
                c1 = fmaf(yRH[m], gc, c1);
            }
            outp[32 * (SCOL / 2)] = pack2(c0, c1);
        }

#pragma unroll
        for (int t = 1; t < 32; t++) {
            float C0 = 0.0f, C1 = 0.0f, S0 = 0.0f, S1 = 0.0f;
#pragma unroll
            for (int m = 0; m < 16; m++) {
                const float gc = alpha64(m) * cos64(m * t);
                const float gs = alpha64(m) * cos64(m * t + 16);
                if (gc != 0.0f) {
                    C0 = fmaf(yRL[m], gc, C0);
                    C1 = fmaf(yRH[m], gc, C1);
                }
                if (gs != 0.0f) {
                    S0 = fmaf(yIL[m], gs, S0);
                    S1 = fmaf(yIH[m], gs, S1);
                }
            }
            outp[(long)t * (SCOL / 2)]        = pack2(C0 + S0, C1 + S1);
            outp[(long)(64 - t) * (SCOL / 2)] = pack2(C0 - S0, C1 - S1);
        }
    }
}

// =====================================================================
extern "C" void kernel_launch(void* const* d_in, const int* in_sizes, int n_in,
                              void* d_out, int out_size) {
    const float* x = (const float*)d_in[0];   // [64][1024][16][64] f32
    const float* w = (const float*)d_in[1];   // [64][64][16][2] f32
    float* out     = (float*)d_out;           // [64][1024][16][64] f32
    (void)in_sizes; (void)n_in; (void)out_size;

    cudaFuncSetAttribute(fused_spectral, cudaFuncAttributeMaxDynamicSharedMemorySize, 65536);

    w_pack<<<512, 256>>>(w);
    fused_spectral<<<NBLK, NTHR, 65536>>>(x, out);
}